// round 2
// baseline (speedup 1.0000x reference)
#include <cuda_runtime.h>
#include <math.h>

#define E_NUM   600000
#define NRAD    6
#define HID     128
#define OUTF    256
#define NLAYERS 3
#define NNODES  50000

// Scratch accumulator for segment_sum: [NNODES][HID] fp32 (25.6 MB, L2-resident).
__device__ float g_hacc[(size_t)NNODES * HID];
__device__ int   g_is64;

// ---------------------------------------------------------------------------
// Detect whether the index tensor is int64 or int32 (JAX x64 flag ambiguity).
// Node ids are in [0, 50000); if int64, every odd 32-bit word is 0.
// ---------------------------------------------------------------------------
__global__ void detect_idx_kernel(const int* __restrict__ idx32) {
    int all0 = 1;
#pragma unroll
    for (int k = 1; k < 33; k += 2) all0 &= (idx32[k] == 0);
    g_is64 = all0;
}

// ---------------------------------------------------------------------------
// Edge stage: g = (rbf @ W_rbf) * x, scatter-add into g_hacc via red.v4.f32.
// One warp per edge; lane handles 4 contiguous hidden channels.
// ---------------------------------------------------------------------------
__global__ void __launch_bounds__(256) edge_kernel(
    const float* __restrict__ x, const float* __restrict__ rbf,
    const void* __restrict__ idx, const float* __restrict__ Wr)
{
    __shared__ float Wsh[NRAD * HID];
    for (int t = threadIdx.x; t < NRAD * HID; t += blockDim.x) Wsh[t] = Wr[t];
    __syncthreads();

    const int is64 = g_is64;
    const int lane = threadIdx.x & 31;
    const int c    = lane * 4;
    const int warp  = blockIdx.x * (blockDim.x >> 5) + (threadIdx.x >> 5);
    const int nwarp = gridDim.x * (blockDim.x >> 5);

    for (int e = warp; e < E_NUM; e += nwarp) {
        const float* rp = rbf + (size_t)e * NRAD;
        float r0 = __ldg(rp + 0), r1 = __ldg(rp + 1), r2 = __ldg(rp + 2);
        float r3 = __ldg(rp + 3), r4 = __ldg(rp + 4), r5 = __ldg(rp + 5);

        long long node = is64 ? ((const long long*)idx)[e]
                              : (long long)((const int*)idx)[e];

        float4 xv = *(const float4*)(x + (size_t)e * HID + c);

        float w0, w1, w2, w3;
        {
            const float* W0 = Wsh + c;
            w0 = r0*W0[0] + r1*W0[HID+0] + r2*W0[2*HID+0] + r3*W0[3*HID+0] + r4*W0[4*HID+0] + r5*W0[5*HID+0];
            w1 = r0*W0[1] + r1*W0[HID+1] + r2*W0[2*HID+1] + r3*W0[3*HID+1] + r4*W0[4*HID+1] + r5*W0[5*HID+1];
            w2 = r0*W0[2] + r1*W0[HID+2] + r2*W0[2*HID+2] + r3*W0[3*HID+2] + r4*W0[4*HID+2] + r5*W0[5*HID+2];
            w3 = r0*W0[3] + r1*W0[HID+3] + r2*W0[2*HID+3] + r3*W0[3*HID+3] + r4*W0[4*HID+3] + r5*W0[5*HID+3];
        }
        float g0 = w0 * xv.x, g1 = w1 * xv.y, g2 = w2 * xv.z, g3 = w3 * xv.w;

        float* dst = g_hacc + (size_t)node * HID + c;
        asm volatile("red.global.add.v4.f32 [%0], {%1,%2,%3,%4};"
                     :: "l"(dst), "f"(g0), "f"(g1), "f"(g2), "f"(g3) : "memory");
    }
}

// ---------------------------------------------------------------------------
// Fused MLP chain per 64-node tile:
//   act = hacc @ W_down; then 3x: act = silu(act @ Ws[l] + bs[l])
// 256 threads, 8x8 register tile per thread, weights staged 16x256/chunk.
// ---------------------------------------------------------------------------
#define TILE_M 64
#define SMEM_FLOATS (TILE_M * OUTF + 16 * OUTF)
#define SMEM_BYTES  (SMEM_FLOATS * 4)

__device__ __forceinline__ float silu_f(float v) {
    return v * (1.0f / (1.0f + __expf(-v)));
}

__device__ __forceinline__ void gemm_tile(
    const float* __restrict__ W, int K,
    const float* __restrict__ act, float* __restrict__ Bt,
    int m0, int tn, int tid, float C[8][8])
{
#pragma unroll
    for (int i = 0; i < 8; i++)
#pragma unroll
        for (int j = 0; j < 8; j++) C[i][j] = 0.f;

    for (int kc = 0; kc < K; kc += 16) {
        __syncthreads();   // protect Bt from previous chunk's readers
        const float4* src = (const float4*)(W + (size_t)kc * OUTF);
#pragma unroll
        for (int v = 0; v < 4; v++)
            ((float4*)Bt)[tid + v * 256] = src[tid + v * 256];
        __syncthreads();

#pragma unroll
        for (int k = 0; k < 16; k++) {
            float a[8];
#pragma unroll
            for (int i = 0; i < 8; i++) a[i] = act[(m0 + i) * OUTF + kc + k];
            float4 b0 = *(const float4*)(Bt + k * OUTF + tn * 4);
            float4 b1 = *(const float4*)(Bt + k * OUTF + 128 + tn * 4);
#pragma unroll
            for (int i = 0; i < 8; i++) {
                C[i][0] += a[i] * b0.x;  C[i][1] += a[i] * b0.y;
                C[i][2] += a[i] * b0.z;  C[i][3] += a[i] * b0.w;
                C[i][4] += a[i] * b1.x;  C[i][5] += a[i] * b1.y;
                C[i][6] += a[i] * b1.z;  C[i][7] += a[i] * b1.w;
            }
        }
    }
    __syncthreads();       // all A reads done before epilogue rewrites act
}

__global__ void __launch_bounds__(256, 2) mlp_kernel(
    const float* __restrict__ Wd, const float* __restrict__ Wl,
    const float* __restrict__ bl, float* __restrict__ out)
{
    extern __shared__ float sm[];
    float* act = sm;                  // [TILE_M][OUTF]
    float* Bt  = sm + TILE_M * OUTF;  // [16][OUTF]

    const int tid = threadIdx.x;
    const int tm  = tid >> 5;         // 0..7
    const int tn  = tid & 31;         // 0..31
    const int m0  = tm * 8;
    const long long nodeBase = (long long)blockIdx.x * TILE_M;

    // Stage input tile hacc[nodeBase : nodeBase+64, 0:128] into act cols 0..127
    for (int v = tid; v < TILE_M * HID / 4; v += 256) {   // 2048 float4s
        int m  = v >> 5;         // 32 float4s per 128-wide row
        int k4 = v & 31;
        long long node = nodeBase + m;
        float4 val = make_float4(0.f, 0.f, 0.f, 0.f);
        if (node < NNODES)
            val = *(const float4*)(g_hacc + (size_t)node * HID + k4 * 4);
        *(float4*)(act + m * OUTF + k4 * 4) = val;
    }

    float C[8][8];

    // GEMM 1: down projection, K=128, no bias/activation
    gemm_tile(Wd, HID, act, Bt, m0, tn, tid, C);
#pragma unroll
    for (int i = 0; i < 8; i++) {
        *(float4*)(act + (m0 + i) * OUTF + tn * 4)       = make_float4(C[i][0], C[i][1], C[i][2], C[i][3]);
        *(float4*)(act + (m0 + i) * OUTF + 128 + tn * 4) = make_float4(C[i][4], C[i][5], C[i][6], C[i][7]);
    }

    // 3 SiLU layers, K=256
    for (int l = 0; l < NLAYERS; l++) {
        gemm_tile(Wl + (size_t)l * OUTF * OUTF, OUTF, act, Bt, m0, tn, tid, C);
        float4 bb0 = *(const float4*)(bl + l * OUTF + tn * 4);
        float4 bb1 = *(const float4*)(bl + l * OUTF + 128 + tn * 4);
#pragma unroll
        for (int i = 0; i < 8; i++) {
            C[i][0] = silu_f(C[i][0] + bb0.x);  C[i][1] = silu_f(C[i][1] + bb0.y);
            C[i][2] = silu_f(C[i][2] + bb0.z);  C[i][3] = silu_f(C[i][3] + bb0.w);
            C[i][4] = silu_f(C[i][4] + bb1.x);  C[i][5] = silu_f(C[i][5] + bb1.y);
            C[i][6] = silu_f(C[i][6] + bb1.z);  C[i][7] = silu_f(C[i][7] + bb1.w);
        }
        if (l < NLAYERS - 1) {
#pragma unroll
            for (int i = 0; i < 8; i++) {
                *(float4*)(act + (m0 + i) * OUTF + tn * 4)       = make_float4(C[i][0], C[i][1], C[i][2], C[i][3]);
                *(float4*)(act + (m0 + i) * OUTF + 128 + tn * 4) = make_float4(C[i][4], C[i][5], C[i][6], C[i][7]);
            }
        } else {
#pragma unroll
            for (int i = 0; i < 8; i++) {
                long long node = nodeBase + m0 + i;
                if (node < NNODES) {
                    *(float4*)(out + (size_t)node * OUTF + tn * 4)       = make_float4(C[i][0], C[i][1], C[i][2], C[i][3]);
                    *(float4*)(out + (size_t)node * OUTF + 128 + tn * 4) = make_float4(C[i][4], C[i][5], C[i][6], C[i][7]);
                }
            }
        }
    }
}

// ---------------------------------------------------------------------------
extern "C" void kernel_launch(void* const* d_in, const int* in_sizes, int n_in,
                              void* d_out, int out_size)
{
    const float* x      = (const float*)d_in[0];
    const float* rbf    = (const float*)d_in[1];
    const void*  idx    = d_in[2];
    const float* W_rbf  = (const float*)d_in[3];
    const float* W_down = (const float*)d_in[4];
    const float* Ws     = (const float*)d_in[5];
    const float* bs     = (const float*)d_in[6];
    float* out = (float*)d_out;

    void* haccPtr = nullptr;
    cudaGetSymbolAddress(&haccPtr, g_hacc);
    cudaMemsetAsync(haccPtr, 0, sizeof(float) * (size_t)NNODES * HID);

    detect_idx_kernel<<<1, 1>>>((const int*)idx);
    edge_kernel<<<2368, 256>>>(x, rbf, idx, W_rbf);

    cudaFuncSetAttribute(mlp_kernel, cudaFuncAttributeMaxDynamicSharedMemorySize, SMEM_BYTES);
    mlp_kernel<<<(NNODES + TILE_M - 1) / TILE_M, 256, SMEM_BYTES>>>(W_down, Ws, bs, out);
}

// round 3
// speedup vs baseline: 1.0026x; 1.0026x over previous
#include <cuda_runtime.h>
#include <math.h>

#define E_NUM   600000
#define NRAD    6
#define HID     128
#define OUTF    256
#define NLAYERS 3
#define NNODES  50000

// Scratch accumulator for segment_sum: [NNODES][HID] fp32 (25.6 MB, L2-resident).
__device__ float g_hacc[(size_t)NNODES * HID];
__device__ int   g_is64;

// ---------------------------------------------------------------------------
// Detect whether the index tensor is int64 or int32 (JAX x64 flag ambiguity).
// Node ids are in [0, 50000); if int64, every odd 32-bit word is 0.
// ---------------------------------------------------------------------------
__global__ void detect_idx_kernel(const int* __restrict__ idx32) {
    int all0 = 1;
#pragma unroll
    for (int k = 1; k < 33; k += 2) all0 &= (idx32[k] == 0);
    g_is64 = all0;
}

// ---------------------------------------------------------------------------
// Edge stage: g = (rbf @ W_rbf) * x, scatter-add into g_hacc via red.v4.f32.
// One warp per edge; lane handles 4 contiguous hidden channels.
// ---------------------------------------------------------------------------
__global__ void __launch_bounds__(256) edge_kernel(
    const float* __restrict__ x, const float* __restrict__ rbf,
    const void* __restrict__ idx, const float* __restrict__ Wr)
{
    __shared__ float Wsh[NRAD * HID];
    for (int t = threadIdx.x; t < NRAD * HID; t += blockDim.x) Wsh[t] = Wr[t];
    __syncthreads();

    const int is64 = g_is64;
    const int lane = threadIdx.x & 31;
    const int c    = lane * 4;
    const int warp  = blockIdx.x * (blockDim.x >> 5) + (threadIdx.x >> 5);
    const int nwarp = gridDim.x * (blockDim.x >> 5);

    for (int e = warp; e < E_NUM; e += nwarp) {
        const float* rp = rbf + (size_t)e * NRAD;
        float r0 = __ldg(rp + 0), r1 = __ldg(rp + 1), r2 = __ldg(rp + 2);
        float r3 = __ldg(rp + 3), r4 = __ldg(rp + 4), r5 = __ldg(rp + 5);

        long long node = is64 ? ((const long long*)idx)[e]
                              : (long long)((const int*)idx)[e];

        float4 xv = *(const float4*)(x + (size_t)e * HID + c);

        float w0, w1, w2, w3;
        {
            const float* W0 = Wsh + c;
            w0 = r0*W0[0] + r1*W0[HID+0] + r2*W0[2*HID+0] + r3*W0[3*HID+0] + r4*W0[4*HID+0] + r5*W0[5*HID+0];
            w1 = r0*W0[1] + r1*W0[HID+1] + r2*W0[2*HID+1] + r3*W0[3*HID+1] + r4*W0[4*HID+1] + r5*W0[5*HID+1];
            w2 = r0*W0[2] + r1*W0[HID+2] + r2*W0[2*HID+2] + r3*W0[3*HID+2] + r4*W0[4*HID+2] + r5*W0[5*HID+2];
            w3 = r0*W0[3] + r1*W0[HID+3] + r2*W0[2*HID+3] + r3*W0[3*HID+3] + r4*W0[4*HID+3] + r5*W0[5*HID+3];
        }
        float g0 = w0 * xv.x, g1 = w1 * xv.y, g2 = w2 * xv.z, g3 = w3 * xv.w;

        float* dst = g_hacc + (size_t)node * HID + c;
        asm volatile("red.global.add.v4.f32 [%0], {%1,%2,%3,%4};"
                     :: "l"(dst), "f"(g0), "f"(g1), "f"(g2), "f"(g3) : "memory");
    }
}

// ---------------------------------------------------------------------------
// Fused MLP chain per 64-node tile:
//   act = hacc @ W_down; then 3x: act = silu(act @ Ws[l] + bs[l])
// 256 threads, 8x8 register tile per thread, weights staged 16x256/chunk.
// ---------------------------------------------------------------------------
#define TILE_M 64
#define SMEM_FLOATS (TILE_M * OUTF + 16 * OUTF)
#define SMEM_BYTES  (SMEM_FLOATS * 4)

__device__ __forceinline__ float silu_f(float v) {
    return v * (1.0f / (1.0f + __expf(-v)));
}

__device__ __forceinline__ void gemm_tile(
    const float* __restrict__ W, int K,
    const float* __restrict__ act, float* __restrict__ Bt,
    int m0, int tn, int tid, float C[8][8])
{
#pragma unroll
    for (int i = 0; i < 8; i++)
#pragma unroll
        for (int j = 0; j < 8; j++) C[i][j] = 0.f;

    for (int kc = 0; kc < K; kc += 16) {
        __syncthreads();   // protect Bt from previous chunk's readers
        const float4* src = (const float4*)(W + (size_t)kc * OUTF);
#pragma unroll
        for (int v = 0; v < 4; v++)
            ((float4*)Bt)[tid + v * 256] = src[tid + v * 256];
        __syncthreads();

#pragma unroll
        for (int k = 0; k < 16; k++) {
            float a[8];
#pragma unroll
            for (int i = 0; i < 8; i++) a[i] = act[(m0 + i) * OUTF + kc + k];
            float4 b0 = *(const float4*)(Bt + k * OUTF + tn * 4);
            float4 b1 = *(const float4*)(Bt + k * OUTF + 128 + tn * 4);
#pragma unroll
            for (int i = 0; i < 8; i++) {
                C[i][0] += a[i] * b0.x;  C[i][1] += a[i] * b0.y;
                C[i][2] += a[i] * b0.z;  C[i][3] += a[i] * b0.w;
                C[i][4] += a[i] * b1.x;  C[i][5] += a[i] * b1.y;
                C[i][6] += a[i] * b1.z;  C[i][7] += a[i] * b1.w;
            }
        }
    }
    __syncthreads();       // all A reads done before epilogue rewrites act
}

__global__ void __launch_bounds__(256, 2) mlp_kernel(
    const float* __restrict__ Wd, const float* __restrict__ Wl,
    const float* __restrict__ bl, float* __restrict__ out)
{
    extern __shared__ float sm[];
    float* act = sm;                  // [TILE_M][OUTF]
    float* Bt  = sm + TILE_M * OUTF;  // [16][OUTF]

    const int tid = threadIdx.x;
    const int tm  = tid >> 5;         // 0..7
    const int tn  = tid & 31;         // 0..31
    const int m0  = tm * 8;
    const long long nodeBase = (long long)blockIdx.x * TILE_M;

    // Stage input tile hacc[nodeBase : nodeBase+64, 0:128] into act cols 0..127
    for (int v = tid; v < TILE_M * HID / 4; v += 256) {   // 2048 float4s
        int m  = v >> 5;         // 32 float4s per 128-wide row
        int k4 = v & 31;
        long long node = nodeBase + m;
        float4 val = make_float4(0.f, 0.f, 0.f, 0.f);
        if (node < NNODES)
            val = *(const float4*)(g_hacc + (size_t)node * HID + k4 * 4);
        *(float4*)(act + m * OUTF + k4 * 4) = val;
    }

    float C[8][8];

    // GEMM 1: down projection, K=128, no bias/activation
    gemm_tile(Wd, HID, act, Bt, m0, tn, tid, C);
#pragma unroll
    for (int i = 0; i < 8; i++) {
        *(float4*)(act + (m0 + i) * OUTF + tn * 4)       = make_float4(C[i][0], C[i][1], C[i][2], C[i][3]);
        *(float4*)(act + (m0 + i) * OUTF + 128 + tn * 4) = make_float4(C[i][4], C[i][5], C[i][6], C[i][7]);
    }

    // 3 SiLU layers, K=256
    for (int l = 0; l < NLAYERS; l++) {
        gemm_tile(Wl + (size_t)l * OUTF * OUTF, OUTF, act, Bt, m0, tn, tid, C);
        float4 bb0 = *(const float4*)(bl + l * OUTF + tn * 4);
        float4 bb1 = *(const float4*)(bl + l * OUTF + 128 + tn * 4);
#pragma unroll
        for (int i = 0; i < 8; i++) {
            C[i][0] = silu_f(C[i][0] + bb0.x);  C[i][1] = silu_f(C[i][1] + bb0.y);
            C[i][2] = silu_f(C[i][2] + bb0.z);  C[i][3] = silu_f(C[i][3] + bb0.w);
            C[i][4] = silu_f(C[i][4] + bb1.x);  C[i][5] = silu_f(C[i][5] + bb1.y);
            C[i][6] = silu_f(C[i][6] + bb1.z);  C[i][7] = silu_f(C[i][7] + bb1.w);
        }
        if (l < NLAYERS - 1) {
#pragma unroll
            for (int i = 0; i < 8; i++) {
                *(float4*)(act + (m0 + i) * OUTF + tn * 4)       = make_float4(C[i][0], C[i][1], C[i][2], C[i][3]);
                *(float4*)(act + (m0 + i) * OUTF + 128 + tn * 4) = make_float4(C[i][4], C[i][5], C[i][6], C[i][7]);
            }
        } else {
#pragma unroll
            for (int i = 0; i < 8; i++) {
                long long node = nodeBase + m0 + i;
                if (node < NNODES) {
                    *(float4*)(out + (size_t)node * OUTF + tn * 4)       = make_float4(C[i][0], C[i][1], C[i][2], C[i][3]);
                    *(float4*)(out + (size_t)node * OUTF + 128 + tn * 4) = make_float4(C[i][4], C[i][5], C[i][6], C[i][7]);
                }
            }
        }
    }
}

// ---------------------------------------------------------------------------
extern "C" void kernel_launch(void* const* d_in, const int* in_sizes, int n_in,
                              void* d_out, int out_size)
{
    const float* x      = (const float*)d_in[0];
    const float* rbf    = (const float*)d_in[1];
    const void*  idx    = d_in[2];
    const float* W_rbf  = (const float*)d_in[3];
    const float* W_down = (const float*)d_in[4];
    const float* Ws     = (const float*)d_in[5];
    const float* bs     = (const float*)d_in[6];
    float* out = (float*)d_out;

    void* haccPtr = nullptr;
    cudaGetSymbolAddress(&haccPtr, g_hacc);
    cudaMemsetAsync(haccPtr, 0, sizeof(float) * (size_t)NNODES * HID);

    detect_idx_kernel<<<1, 1>>>((const int*)idx);
    edge_kernel<<<2368, 256>>>(x, rbf, idx, W_rbf);

    cudaFuncSetAttribute(mlp_kernel, cudaFuncAttributeMaxDynamicSharedMemorySize, SMEM_BYTES);
    mlp_kernel<<<(NNODES + TILE_M - 1) / TILE_M, 256, SMEM_BYTES>>>(W_down, Ws, bs, out);
}

// round 7
// speedup vs baseline: 2.4296x; 2.4233x over previous
#include <cuda_runtime.h>
#include <cuda_fp16.h>
#include <math.h>

#define E_NUM   600000
#define NRAD    6
#define HID     128
#define NNODES  50000
#define NT      392

__device__ float g_hacc[(size_t)NNODES * HID];
__device__ __align__(256) __half g_wimg[14 * 16384];   // 14 chunk-tiles x 32KB (fp16, swizzled, W^T)

// ---------------- helpers ----------------
__device__ __forceinline__ void cpa16(void* dst, const void* src) {
    unsigned d = (unsigned)__cvta_generic_to_shared(dst);
    asm volatile("cp.async.cg.shared.global [%0], [%1], 16;" :: "r"(d), "l"(src));
}
#define CP_COMMIT() asm volatile("cp.async.commit_group;" ::: "memory")
#define CP_WAIT1()  asm volatile("cp.async.wait_group 1;" ::: "memory")
#define CP_WAIT0()  asm volatile("cp.async.wait_group 0;" ::: "memory")

__device__ __forceinline__ void mma16816(float* c, const unsigned* a, unsigned b0, unsigned b1) {
    asm volatile("mma.sync.aligned.m16n8k16.row.col.f32.f16.f16.f32 "
                 "{%0,%1,%2,%3}, {%4,%5,%6,%7}, {%8,%9}, {%0,%1,%2,%3};"
                 : "+f"(c[0]), "+f"(c[1]), "+f"(c[2]), "+f"(c[3])
                 : "r"(a[0]), "r"(a[1]), "r"(a[2]), "r"(a[3]), "r"(b0), "r"(b1));
}
__device__ __forceinline__ unsigned packh2(float x, float y) {
    __half2 h = __floats2half2_rn(x, y);
    return *(unsigned*)&h;
}
__device__ __forceinline__ float silu_f(float v) { return v * (1.0f/(1.0f+__expf(-v))); }

// act[m][k] fp16, 128 rows x 256 cols, 512B/row, XOR-swizzled 16B blocks
__device__ __forceinline__ int act_off(int m, int k) {
    return m*512 + ((((k>>3) ^ (m&7)) << 4) + (k&7)*2);
}
// B smem: Wt chunk [n=256][kc=64] fp16, 128B/row, swizzled
__device__ __forceinline__ int b_off(int n, int kc) {
    return n*128 + ((((kc>>3) ^ (n&7)) << 4) + (kc&7)*2);
}

// ---------------- prep: zero hacc + build fp16 W^T swizzled chunk images ----
__global__ void __launch_bounds__(256) prep_kernel(const float* __restrict__ Wd,
                                                   const float* __restrict__ Ws)
{
    size_t stride = (size_t)gridDim.x * blockDim.x;
    size_t t0 = (size_t)blockIdx.x * blockDim.x + threadIdx.x;
    float4 z = make_float4(0.f,0.f,0.f,0.f);
    for (size_t v = t0; v < (size_t)NNODES*HID/4; v += stride) ((float4*)g_hacc)[v] = z;
    for (size_t e = t0; e < 229376; e += stride) {
        int l, k, n;
        if (e < 32768) { l = 0; k = (int)(e >> 8); n = (int)(e & 255); }
        else { size_t r = e - 32768; l = 1 + (int)(r >> 16); k = (int)((r >> 8) & 255); n = (int)(r & 255); }
        float w = (l == 0) ? Wd[k*256+n] : Ws[(size_t)(l-1)*65536 + k*256 + n];
        int chunk = k >> 6, kc = k & 63;
        int tile = (l == 0) ? chunk : 2 + (l-1)*4 + chunk;
        int dst = n*64 + (((kc>>3) ^ (n&7)) << 3) + (kc&7);
        g_wimg[(size_t)tile*16384 + dst] = __float2half_rn(w);
    }
}

// ---------------- edge stage ----------------
__global__ void __launch_bounds__(256) edge_kernel(
    const float* __restrict__ x, const float* __restrict__ rbf,
    const void* __restrict__ idx, const float* __restrict__ Wr)
{
    __shared__ float Wsh[NRAD * HID];
    __shared__ int s64;
    if (threadIdx.x == 0) {
        int a = 1; const int* p = (const int*)idx;
        for (int k = 1; k < 64; k += 2) a &= (p[k] == 0);
        s64 = a;
    }
    for (int t = threadIdx.x; t < NRAD*HID; t += blockDim.x) Wsh[t] = Wr[t];
    __syncthreads();
    const int is64 = s64;
    const int c = (threadIdx.x & 31) * 4;
    const int warp = blockIdx.x*(blockDim.x>>5) + (threadIdx.x>>5);
    const int nwarp = gridDim.x*(blockDim.x>>5);
    for (int e = warp; e < E_NUM; e += nwarp) {
        const float* rp = rbf + (size_t)e * NRAD;
        float r0=__ldg(rp),r1=__ldg(rp+1),r2=__ldg(rp+2),r3=__ldg(rp+3),r4=__ldg(rp+4),r5=__ldg(rp+5);
        long long node = is64 ? ((const long long*)idx)[e] : (long long)((const int*)idx)[e];
        float4 xv = *(const float4*)(x + (size_t)e*HID + c);
        const float* W0 = Wsh + c;
        float w0=r0*W0[0]+r1*W0[HID]+r2*W0[2*HID]+r3*W0[3*HID]+r4*W0[4*HID]+r5*W0[5*HID];
        float w1=r0*W0[1]+r1*W0[HID+1]+r2*W0[2*HID+1]+r3*W0[3*HID+1]+r4*W0[4*HID+1]+r5*W0[5*HID+1];
        float w2=r0*W0[2]+r1*W0[HID+2]+r2*W0[2*HID+2]+r3*W0[3*HID+2]+r4*W0[4*HID+2]+r5*W0[5*HID+2];
        float w3=r0*W0[3]+r1*W0[HID+3]+r2*W0[2*HID+3]+r3*W0[3*HID+3]+r4*W0[4*HID+3]+r5*W0[5*HID+3];
        float* dst = g_hacc + (size_t)node*HID + c;
        asm volatile("red.global.add.v4.f32 [%0], {%1,%2,%3,%4};"
                     :: "l"(dst), "f"(w0*xv.x), "f"(w1*xv.y), "f"(w2*xv.z), "f"(w3*xv.w) : "memory");
    }
}

// ---------------- MLP on mma.sync fp16 ----------------
#define SMEM_DYN (65536 + 2*32768)

__global__ void __launch_bounds__(256, 1) mlp_kernel(const float* __restrict__ bs,
                                                     float* __restrict__ out)
{
    extern __shared__ char dsm[];
    char* act = dsm;                 // 64KB: 128 x 256 fp16 swizzled
    char* bbuf[2] = { dsm + 65536, dsm + 65536 + 32768 };

    const int tid  = threadIdx.x;
    const int wid  = tid >> 5, lane = tid & 31;
    const int wm   = wid >> 2;        // 0..1  (M half)
    const int wn   = wid & 3;         // 0..3  (N quarter)
    const int gr   = lane >> 2;       // 0..7
    const int gc   = lane & 3;        // 0..3
    const int nodeBase = blockIdx.x * 128;

    // ---- stage layer-0 A: hacc fp32 -> fp16 swizzled act (cols 0..127)
    {
        int row  = tid >> 1;
        int half = tid & 1;
        int node = nodeBase + row;
        bool ok  = (node < NNODES);
        const float4* src = (const float4*)(g_hacc + (size_t)node * HID);
#pragma unroll
        for (int w4 = 0; w4 < 16; w4++) {
            int k0 = half*64 + w4*4;
            float4 v = ok ? __ldg(&src[k0 >> 2]) : make_float4(0.f,0.f,0.f,0.f);
            *(unsigned*)(act + act_off(row, k0))     = packh2(v.x, v.y);
            *(unsigned*)(act + act_off(row, k0 + 2)) = packh2(v.z, v.w);
        }
    }
    __syncthreads();

    for (int l = 0; l < 4; l++) {
        const int nch   = (l == 0) ? 2 : 4;
        const int tbase = (l == 0) ? 0 : 2 + (l-1)*4;

        float C[4][8][4];
#pragma unroll
        for (int i=0;i<4;i++)
#pragma unroll
            for (int j=0;j<8;j++) { C[i][j][0]=0.f; C[i][j][1]=0.f; C[i][j][2]=0.f; C[i][j][3]=0.f; }

        // prefetch chunk 0
        {
            const char* src = (const char*)(g_wimg + (size_t)tbase*16384) + tid*16;
#pragma unroll
            for (int q = 0; q < 8; q++) cpa16(bbuf[0] + tid*16 + q*4096, src + q*4096);
            CP_COMMIT();
        }

        for (int c = 0; c < nch; c++) {
            const int b = c & 1;
            if (c + 1 < nch) {
                const char* src = (const char*)(g_wimg + (size_t)(tbase+c+1)*16384) + tid*16;
#pragma unroll
                for (int q = 0; q < 8; q++) cpa16(bbuf[b^1] + tid*16 + q*4096, src + q*4096);
                CP_COMMIT();
                CP_WAIT1();
            } else CP_WAIT0();
            __syncthreads();

            const char* bb = bbuf[b];
#pragma unroll
            for (int kk = 0; kk < 4; kk++) {
                const int kb = c*64 + kk*16;     // global k in act
                const int kc = kk*16;            // k within chunk
                unsigned a[4][4];
#pragma unroll
                for (int i = 0; i < 4; i++) {
                    int m = wm*64 + i*16 + gr;
                    a[i][0] = *(const unsigned*)(act + act_off(m,     kb     + gc*2));
                    a[i][1] = *(const unsigned*)(act + act_off(m + 8, kb     + gc*2));
                    a[i][2] = *(const unsigned*)(act + act_off(m,     kb + 8 + gc*2));
                    a[i][3] = *(const unsigned*)(act + act_off(m + 8, kb + 8 + gc*2));
                }
#pragma unroll
                for (int j = 0; j < 8; j++) {
                    int n = wn*64 + j*8 + gr;    // gr = lane>>2 is B's n index
                    unsigned b0 = *(const unsigned*)(bb + b_off(n, kc     + gc*2));
                    unsigned b1 = *(const unsigned*)(bb + b_off(n, kc + 8 + gc*2));
#pragma unroll
                    for (int i = 0; i < 4; i++) mma16816(C[i][j], a[i], b0, b1);
                }
            }
            __syncthreads();   // all reads of bbuf[b] done before it is refilled
        }

        // ---- epilogue
        if (l < 3) {
            // act is fully consumed (last sync above); rewrite with layer output
#pragma unroll
            for (int i = 0; i < 4; i++) {
                int r0 = wm*64 + i*16 + gr;
#pragma unroll
                for (int j = 0; j < 8; j++) {
                    int n0 = wn*64 + j*8 + gc*2;
                    float v00=C[i][j][0], v01=C[i][j][1], v10=C[i][j][2], v11=C[i][j][3];
                    if (l > 0) {
                        float b0 = __ldg(bs + (l-1)*256 + n0), b1 = __ldg(bs + (l-1)*256 + n0 + 1);
                        v00 = silu_f(v00 + b0); v01 = silu_f(v01 + b1);
                        v10 = silu_f(v10 + b0); v11 = silu_f(v11 + b1);
                    }
                    *(unsigned*)(act + act_off(r0,     n0)) = packh2(v00, v01);
                    *(unsigned*)(act + act_off(r0 + 8, n0)) = packh2(v10, v11);
                }
            }
            __syncthreads();
        } else {
#pragma unroll
            for (int i = 0; i < 4; i++) {
                int r0 = wm*64 + i*16 + gr;
                int n0base = wn*64;
                long long node0 = nodeBase + r0, node1 = node0 + 8;
#pragma unroll
                for (int j = 0; j < 8; j++) {
                    int n0 = n0base + j*8 + gc*2;
                    float b0 = __ldg(bs + 512 + n0), b1 = __ldg(bs + 512 + n0 + 1);
                    if (node0 < NNODES) {
                        float* op = out + (size_t)node0*256 + n0;
                        op[0] = silu_f(C[i][j][0] + b0);
                        op[1] = silu_f(C[i][j][1] + b1);
                    }
                    if (node1 < NNODES) {
                        float* op = out + (size_t)node1*256 + n0;
                        op[0] = silu_f(C[i][j][2] + b0);
                        op[1] = silu_f(C[i][j][3] + b1);
                    }
                }
            }
        }
    }
}

// ---------------------------------------------------------------------------
extern "C" void kernel_launch(void* const* d_in, const int* in_sizes, int n_in,
                              void* d_out, int out_size)
{
    const float* x      = (const float*)d_in[0];
    const float* rbf    = (const float*)d_in[1];
    const void*  idx    = d_in[2];
    const float* W_rbf  = (const float*)d_in[3];
    const float* W_down = (const float*)d_in[4];
    const float* Ws     = (const float*)d_in[5];
    const float* bs     = (const float*)d_in[6];
    float* out = (float*)d_out;

    prep_kernel<<<448, 256>>>(W_down, Ws);
    edge_kernel<<<2368, 256>>>(x, rbf, idx, W_rbf);
    cudaFuncSetAttribute(mlp_kernel, cudaFuncAttributeMaxDynamicSharedMemorySize, SMEM_DYN);
    mlp_kernel<<<NT, 256, SMEM_DYN>>>(bs, out);
}

// round 8
// speedup vs baseline: 2.9326x; 1.2070x over previous
#include <cuda_runtime.h>
#include <cuda_fp16.h>
#include <math.h>

#define E_NUM   600000
#define NRAD    6
#define HID     128
#define NNODES  50000
#define NT      782          // 64-node tiles

__device__ float g_hacc[(size_t)NNODES * HID];
__device__ __align__(256) __half g_wimg[14 * 16384];   // 14 chunk-tiles x 32KB (fp16, swizzled, W^T)

// ---------------- helpers ----------------
__device__ __forceinline__ void cpa16(void* dst, const void* src) {
    unsigned d = (unsigned)__cvta_generic_to_shared(dst);
    asm volatile("cp.async.cg.shared.global [%0], [%1], 16;" :: "r"(d), "l"(src));
}
#define CP_COMMIT() asm volatile("cp.async.commit_group;" ::: "memory")
#define CP_WAIT1()  asm volatile("cp.async.wait_group 1;" ::: "memory")
#define CP_WAIT0()  asm volatile("cp.async.wait_group 0;" ::: "memory")

__device__ __forceinline__ void mma16816(float* c, const unsigned* a, unsigned b0, unsigned b1) {
    asm volatile("mma.sync.aligned.m16n8k16.row.col.f32.f16.f16.f32 "
                 "{%0,%1,%2,%3}, {%4,%5,%6,%7}, {%8,%9}, {%0,%1,%2,%3};"
                 : "+f"(c[0]), "+f"(c[1]), "+f"(c[2]), "+f"(c[3])
                 : "r"(a[0]), "r"(a[1]), "r"(a[2]), "r"(a[3]), "r"(b0), "r"(b1));
}
__device__ __forceinline__ unsigned packh2(float x, float y) {
    __half2 h = __floats2half2_rn(x, y);
    return *(unsigned*)&h;
}
__device__ __forceinline__ float silu_f(float v) { return v * (1.0f/(1.0f+__expf(-v))); }

// act[m][k] fp16, 64 rows x 256 cols, 512B/row, XOR-swizzled 16B blocks
__device__ __forceinline__ int act_off(int m, int k) {
    return m*512 + ((((k>>3) ^ (m&7)) << 4) + (k&7)*2);
}
// B smem: Wt chunk [n=256][kc=64] fp16, 128B/row, swizzled
__device__ __forceinline__ int b_off(int n, int kc) {
    return n*128 + ((((kc>>3) ^ (n&7)) << 4) + (kc&7)*2);
}

// ---------------- prep: zero hacc + build fp16 W^T swizzled chunk images ----
__global__ void __launch_bounds__(256) prep_kernel(const float* __restrict__ Wd,
                                                   const float* __restrict__ Ws)
{
    size_t stride = (size_t)gridDim.x * blockDim.x;
    size_t t0 = (size_t)blockIdx.x * blockDim.x + threadIdx.x;
    float4 z = make_float4(0.f,0.f,0.f,0.f);
    for (size_t v = t0; v < (size_t)NNODES*HID/4; v += stride) ((float4*)g_hacc)[v] = z;
    for (size_t e = t0; e < 229376; e += stride) {
        int l, k, n;
        if (e < 32768) { l = 0; k = (int)(e >> 8); n = (int)(e & 255); }
        else { size_t r = e - 32768; l = 1 + (int)(r >> 16); k = (int)((r >> 8) & 255); n = (int)(r & 255); }
        float w = (l == 0) ? Wd[k*256+n] : Ws[(size_t)(l-1)*65536 + k*256 + n];
        int chunk = k >> 6, kc = k & 63;
        int tile = (l == 0) ? chunk : 2 + (l-1)*4 + chunk;
        int dst = n*64 + (((kc>>3) ^ (n&7)) << 3) + (kc&7);
        g_wimg[(size_t)tile*16384 + dst] = __float2half_rn(w);
    }
}

// ---------------- edge stage: streaming loads (evict-first), L2-resident atomics
__global__ void __launch_bounds__(256) edge_kernel(
    const float* __restrict__ x, const float* __restrict__ rbf,
    const void* __restrict__ idx, const float* __restrict__ Wr)
{
    __shared__ float Wsh[NRAD * HID];
    __shared__ int s64;
    if (threadIdx.x == 0) {
        int a = 1; const int* p = (const int*)idx;
        for (int k = 1; k < 64; k += 2) a &= (p[k] == 0);
        s64 = a;
    }
    for (int t = threadIdx.x; t < NRAD*HID; t += blockDim.x) Wsh[t] = Wr[t];
    __syncthreads();
    const int is64 = s64;
    const int c = (threadIdx.x & 31) * 4;
    const int warp = blockIdx.x*(blockDim.x>>5) + (threadIdx.x>>5);
    const int nwarp = gridDim.x*(blockDim.x>>5);
    for (int e = warp; e < E_NUM; e += nwarp) {
        const float* rp = rbf + (size_t)e * NRAD;
        float r0=__ldcs(rp),r1=__ldcs(rp+1),r2=__ldcs(rp+2),
              r3=__ldcs(rp+3),r4=__ldcs(rp+4),r5=__ldcs(rp+5);
        long long node = is64 ? __ldcs((const long long*)idx + e)
                              : (long long)__ldcs((const int*)idx + e);
        float4 xv = __ldcs((const float4*)(x + (size_t)e*HID + c));
        const float* W0 = Wsh + c;
        float w0=r0*W0[0]+r1*W0[HID]+r2*W0[2*HID]+r3*W0[3*HID]+r4*W0[4*HID]+r5*W0[5*HID];
        float w1=r0*W0[1]+r1*W0[HID+1]+r2*W0[2*HID+1]+r3*W0[3*HID+1]+r4*W0[4*HID+1]+r5*W0[5*HID+1];
        float w2=r0*W0[2]+r1*W0[HID+2]+r2*W0[2*HID+2]+r3*W0[3*HID+2]+r4*W0[4*HID+2]+r5*W0[5*HID+2];
        float w3=r0*W0[3]+r1*W0[HID+3]+r2*W0[2*HID+3]+r3*W0[3*HID+3]+r4*W0[4*HID+3]+r5*W0[5*HID+3];
        float* dst = g_hacc + (size_t)node*HID + c;
        asm volatile("red.global.add.v4.f32 [%0], {%1,%2,%3,%4};"
                     :: "l"(dst), "f"(w0*xv.x), "f"(w1*xv.y), "f"(w2*xv.z), "f"(w3*xv.w) : "memory");
    }
}

// ---------------- MLP on mma.sync fp16, 64-node tiles, 2 CTAs/SM ----------------
#define SMEM_DYN (32768 + 2*32768)

__global__ void __launch_bounds__(256, 2) mlp_kernel(const float* __restrict__ bs,
                                                     float* __restrict__ out)
{
    extern __shared__ char dsm[];
    char* act = dsm;                 // 32KB: 64 x 256 fp16 swizzled
    char* bbuf[2] = { dsm + 32768, dsm + 65536 };

    const int tid  = threadIdx.x;
    const int wid  = tid >> 5, lane = tid & 31;
    const int wm   = wid >> 2;        // 0..1  (32-row half)
    const int wn   = wid & 3;         // 0..3  (64-col quarter)
    const int gr   = lane >> 2;       // 0..7
    const int gc   = lane & 3;        // 0..3
    const int nodeBase = blockIdx.x * 64;

    // ---- stage layer-0 A: hacc fp32 -> fp16 swizzled act (cols 0..127)
    {
        int row = tid >> 2;           // 0..63
        int q   = tid & 3;            // 32-col quarter
        int node = nodeBase + row;
        bool ok  = (node < NNODES);
        const float4* src = (const float4*)(g_hacc + (size_t)node * HID);
#pragma unroll
        for (int w4 = 0; w4 < 8; w4++) {
            int k0 = q*32 + w4*4;
            float4 v = ok ? __ldg(&src[k0 >> 2]) : make_float4(0.f,0.f,0.f,0.f);
            *(unsigned*)(act + act_off(row, k0))     = packh2(v.x, v.y);
            *(unsigned*)(act + act_off(row, k0 + 2)) = packh2(v.z, v.w);
        }
    }
    __syncthreads();

    for (int l = 0; l < 4; l++) {
        const int nch   = (l == 0) ? 2 : 4;
        const int tbase = (l == 0) ? 0 : 2 + (l-1)*4;

        float C[2][8][4];
#pragma unroll
        for (int i=0;i<2;i++)
#pragma unroll
            for (int j=0;j<8;j++) { C[i][j][0]=0.f; C[i][j][1]=0.f; C[i][j][2]=0.f; C[i][j][3]=0.f; }

        // prefetch chunk 0
        {
            const char* src = (const char*)(g_wimg + (size_t)tbase*16384) + tid*16;
#pragma unroll
            for (int q = 0; q < 8; q++) cpa16(bbuf[0] + tid*16 + q*4096, src + q*4096);
            CP_COMMIT();
        }

        for (int c = 0; c < nch; c++) {
            const int b = c & 1;
            if (c + 1 < nch) {
                const char* src = (const char*)(g_wimg + (size_t)(tbase+c+1)*16384) + tid*16;
#pragma unroll
                for (int q = 0; q < 8; q++) cpa16(bbuf[b^1] + tid*16 + q*4096, src + q*4096);
                CP_COMMIT();
                CP_WAIT1();
            } else CP_WAIT0();
            __syncthreads();

            const char* bb = bbuf[b];
#pragma unroll
            for (int kk = 0; kk < 4; kk++) {
                const int kb = c*64 + kk*16;     // global k in act
                const int kc = kk*16;            // k within chunk
                unsigned a[2][4];
#pragma unroll
                for (int i = 0; i < 2; i++) {
                    int m = wm*32 + i*16 + gr;
                    a[i][0] = *(const unsigned*)(act + act_off(m,     kb     + gc*2));
                    a[i][1] = *(const unsigned*)(act + act_off(m + 8, kb     + gc*2));
                    a[i][2] = *(const unsigned*)(act + act_off(m,     kb + 8 + gc*2));
                    a[i][3] = *(const unsigned*)(act + act_off(m + 8, kb + 8 + gc*2));
                }
#pragma unroll
                for (int j = 0; j < 8; j++) {
                    int n = wn*64 + j*8 + gr;
                    unsigned b0 = *(const unsigned*)(bb + b_off(n, kc     + gc*2));
                    unsigned b1 = *(const unsigned*)(bb + b_off(n, kc + 8 + gc*2));
#pragma unroll
                    for (int i = 0; i < 2; i++) mma16816(C[i][j], a[i], b0, b1);
                }
            }
            __syncthreads();   // all reads of bbuf[b] done before it is refilled
        }

        // ---- epilogue
        if (l < 3) {
#pragma unroll
            for (int i = 0; i < 2; i++) {
                int r0 = wm*32 + i*16 + gr;
#pragma unroll
                for (int j = 0; j < 8; j++) {
                    int n0 = wn*64 + j*8 + gc*2;
                    float v00=C[i][j][0], v01=C[i][j][1], v10=C[i][j][2], v11=C[i][j][3];
                    if (l > 0) {
                        float b0 = __ldg(bs + (l-1)*256 + n0), b1 = __ldg(bs + (l-1)*256 + n0 + 1);
                        v00 = silu_f(v00 + b0); v01 = silu_f(v01 + b1);
                        v10 = silu_f(v10 + b0); v11 = silu_f(v11 + b1);
                    }
                    *(unsigned*)(act + act_off(r0,     n0)) = packh2(v00, v01);
                    *(unsigned*)(act + act_off(r0 + 8, n0)) = packh2(v10, v11);
                }
            }
            __syncthreads();
        } else {
#pragma unroll
            for (int i = 0; i < 2; i++) {
                int r0 = wm*32 + i*16 + gr;
                long long node0 = nodeBase + r0, node1 = node0 + 8;
#pragma unroll
                for (int j = 0; j < 8; j++) {
                    int n0 = wn*64 + j*8 + gc*2;
                    float b0 = __ldg(bs + 512 + n0), b1 = __ldg(bs + 512 + n0 + 1);
                    if (node0 < NNODES) {
                        float* op = out + (size_t)node0*256 + n0;
                        op[0] = silu_f(C[i][j][0] + b0);
                        op[1] = silu_f(C[i][j][1] + b1);
                    }
                    if (node1 < NNODES) {
                        float* op = out + (size_t)node1*256 + n0;
                        op[0] = silu_f(C[i][j][2] + b0);
                        op[1] = silu_f(C[i][j][3] + b1);
                    }
                }
            }
        }
    }
}

// ---------------------------------------------------------------------------
extern "C" void kernel_launch(void* const* d_in, const int* in_sizes, int n_in,
                              void* d_out, int out_size)
{
    const float* x      = (const float*)d_in[0];
    const float* rbf    = (const float*)d_in[1];
    const void*  idx    = d_in[2];
    const float* W_rbf  = (const float*)d_in[3];
    const float* W_down = (const float*)d_in[4];
    const float* Ws     = (const float*)d_in[5];
    const float* bs     = (const float*)d_in[6];
    float* out = (float*)d_out;

    prep_kernel<<<448, 256>>>(W_down, Ws);
    edge_kernel<<<2368, 256>>>(x, rbf, idx, W_rbf);
    cudaFuncSetAttribute(mlp_kernel, cudaFuncAttributeMaxDynamicSharedMemorySize, SMEM_DYN);
    mlp_kernel<<<NT, 256, SMEM_DYN>>>(bs, out);
}